// round 12
// baseline (speedup 1.0000x reference)
#include <cuda_runtime.h>
#include <cstdint>

// Problem constants (fixed by setup_inputs: audio (8, 80000) fp32)
#define BATCH   8
#define TLEN    80000
#define KFRM    250
#define FRAME   320
#define LAGS    189
#define LAG_MIN 5
#define HALFSZ  94             // LAGS // 2
#define SEGLEN  509            // FRAME + LAGS
#define NOUT    235
#define WINMED  30
#define PADM    14
#define EPSF    1e-9f

// nccf kernel blocking: ONE frame per block, 96 threads (3 warps), grid 2000
#define TPF   24               // lag-groups per frame (8 lags each, 192 padded)
#define KSPL  4                // split-K factor (threads per lag-group)
#define NTHR  (TPF * KSPL)     // 96 threads
#define NLAGP 192
#define SEGL  520              // logical padded segment length
#define SEGP  584              // physical (skewed) words per frame

// output layout (float32): f0[B*NOUT], whiten[B*NOUT], voiced[B*NOUT], energy[B*KFRM]
#define OFF_F0     0
#define OFF_WHITEN (BATCH * NOUT)
#define OFF_VOICED (2 * BATCH * NOUT)
#define OFF_ENERGY (3 * BATCH * NOUT)

__device__ int g_idx[BATCH * KFRM];

typedef unsigned long long ull;

__device__ __forceinline__ int skew(int m) { return m + ((m >> 5) << 2); }

__device__ __forceinline__ ull pk(float lo, float hi) {
    ull r; asm("mov.b64 %0, {%1, %2};" : "=l"(r) : "f"(lo), "f"(hi)); return r;
}
__device__ __forceinline__ void upk(float& lo, float& hi, ull v) {
    asm("mov.b64 {%0, %1}, %2;" : "=f"(lo), "=f"(hi) : "l"(v));
}
__device__ __forceinline__ void ffma2(ull& d, ull a, ull b) {
    asm("fma.rn.f32x2 %0, %1, %2, %0;" : "+l"(d) : "l"(a), "l"(b));
}

// ---------------------------------------------------------------------------
// Kernel 1 (UNCHANGED from round 11, 11.8us): NCCF + argmax + energy.
// ONE frame per block, 96 threads, grid 2000. Prefix-sum-of-x^2 for norms;
// mainloop 16 FFMA2/step fully unrolled; 4 K-partials combined via shfl_xor.
// ---------------------------------------------------------------------------
__global__ void __launch_bounds__(NTHR) nccf_kernel(const float* __restrict__ audio,
                                                    float* __restrict__ out) {
    __shared__ __align__(16) float seg[SEGP];
    __shared__ float P[516];          // P[j] = sum_{i<j} x_i^2, j in [0, 510]
    __shared__ float wsum[3];
    __shared__ float sval[NLAGP];

    const int tid  = threadIdx.x;
    const int warp = tid >> 5;
    const int lane = tid & 31;
    const int fr   = blockIdx.x;           // frame id = b*KFRM + k

    // Stage this frame (skewed layout, zero-padded)
    {
        const int b = fr / KFRM;
        const int k = fr - b * KFRM;
        const float* row  = audio + (size_t)b * TLEN;
        const int    base = k * FRAME;
        for (int j = tid; j < SEGL; j += NTHR) {
            float v = 0.0f;
            if (j < SEGLEN && base + j < TLEN) v = row[base + j];
            seg[skew(j)] = v;
        }
    }
    __syncthreads();

    // Prefix sum of x^2 over j in [0, 510): thread owns 6 elements
    {
        const int j0 = tid * 6;
        float pre[6];
        float sum = 0.0f;
        #pragma unroll
        for (int k = 0; k < 6; k++) {
            float x = 0.0f;
            if (j0 + k < 510) x = seg[skew(j0 + k)];
            sum = fmaf(x, x, sum);
            pre[k] = sum;
        }
        float sc = sum;   // inclusive warp scan of per-thread totals
        #pragma unroll
        for (int d = 1; d < 32; d <<= 1) {
            float o = __shfl_up_sync(0xffffffffu, sc, d);
            if (lane >= d) sc += o;
        }
        if (lane == 31) wsum[warp] = sc;
        __syncthreads();
        float base = sc - sum;
        if (warp >= 1) base += wsum[0];
        if (warp >= 2) base += wsum[1];
        if (tid == 0) P[0] = 0.0f;
        #pragma unroll
        for (int k = 0; k < 6; k++)
            if (j0 + k < 510) P[j0 + k + 1] = base + pre[k];
    }
    __syncthreads();

    {
        const int h  = tid & 3;                 // K-chunk
        const int g  = tid >> 2;                // lag-group 0..23
        const float* sf = seg;
        const int gb = 8 * g;
        const int sb = 20 * h;                  // window-step base

        ull c0 = 0, c1 = 0, c2 = 0, c3 = 0, c4 = 0, c5 = 0, c6 = 0, c7 = 0;
        float4 W1;
        ull O0, O1, O2, E1, E2, E3;
        {
            float4 W0 = *reinterpret_cast<const float4*>(sf + skew(gb + 4 * sb));
            W1        = *reinterpret_cast<const float4*>(sf + skew(gb + 4 * sb + 4));
            O0 = pk(W0.y, W0.z); O1 = pk(W0.w, W1.x); O2 = pk(W1.y, W1.z);
            E1 = pk(W0.z, W0.w); E2 = pk(W1.x, W1.y); E3 = pk(W1.z, W1.w);
        }

        #pragma unroll
        for (int s = 0; s < 20; s++) {
            float4 Aq = *reinterpret_cast<const float4*>(sf + skew(4 * (sb + s)));
            ull A01 = pk(Aq.x, Aq.y);
            ull A23 = pk(Aq.z, Aq.w);
            float4 W2 = *reinterpret_cast<const float4*>(sf + skew(gb + 8 + 4 * (sb + s)));

            ull O3 = pk(W1.w, W2.x);
            ull E4 = pk(W2.x, W2.y);
            ull O4 = pk(W2.y, W2.z);
            ull E5 = pk(W2.z, W2.w);

            ffma2(c0, A01, O0); ffma2(c0, A23, O1);
            ffma2(c1, A01, E1); ffma2(c1, A23, E2);
            ffma2(c2, A01, O1); ffma2(c2, A23, O2);
            ffma2(c3, A01, E2); ffma2(c3, A23, E3);
            ffma2(c4, A01, O2); ffma2(c4, A23, O3);
            ffma2(c5, A01, E3); ffma2(c5, A23, E4);
            ffma2(c6, A01, O3); ffma2(c6, A23, O4);
            ffma2(c7, A01, E4); ffma2(c7, A23, E5);

            O0 = O2; O1 = O3; O2 = O4;
            E1 = E3; E2 = E4; E3 = E5;
            W1 = W2;
        }

        // Reduce packed pairs to scalars, then combine K-partials via shfl.
        float cr[8];
        { float lo, hi;
          upk(lo, hi, c0); cr[0] = lo + hi; upk(lo, hi, c1); cr[1] = lo + hi;
          upk(lo, hi, c2); cr[2] = lo + hi; upk(lo, hi, c3); cr[3] = lo + hi;
          upk(lo, hi, c4); cr[4] = lo + hi; upk(lo, hi, c5); cr[5] = lo + hi;
          upk(lo, hi, c6); cr[6] = lo + hi; upk(lo, hi, c7); cr[7] = lo + hi; }
        #pragma unroll
        for (int d = 1; d <= 2; d <<= 1) {
            #pragma unroll
            for (int l = 0; l < 8; l++)
                cr[l] += __shfl_xor_sync(0xffffffffu, cr[l], d);
        }

        // norms from prefix sums; each h-thread writes 2 of the 8 lags
        #pragma unroll
        for (int l = 2 * h; l < 2 * h + 2; l++) {
            int t = gb + l;
            float n2 = fmaxf(P[t + 321] - P[t + 1], 0.0f);
            float d  = EPSF + sqrtf(n2);
            sval[t] = __fdividef(cr[l], d * d);
        }

        if (tid == 0)
            out[OFF_ENERGY + fr] = P[320] * (1.0f / FRAME);
    }
    __syncthreads();

    // Argmax (warp 0, first-occurrence semantics)
    if (warp == 0) {
        float bv = -3.0e38f; int bi = 1 << 30;
        float hv = -3.0e38f; int hi = 1 << 30;
        for (int t = LAG_MIN + lane; t < LAGS; t += 32) {
            float x = sval[t];
            if (x > bv) { bv = x; bi = t; }
            if (t < HALFSZ && x > hv) { hv = x; hi = t; }
        }
        #pragma unroll
        for (int off = 16; off; off >>= 1) {
            float ov  = __shfl_down_sync(0xffffffffu, bv, off);
            int   oi  = __shfl_down_sync(0xffffffffu, bi, off);
            if (ov > bv || (ov == bv && oi < bi)) { bv = ov; bi = oi; }
            float ohv = __shfl_down_sync(0xffffffffu, hv, off);
            int   ohi = __shfl_down_sync(0xffffffffu, hi, off);
            if (ohv > hv || (ohv == hv && ohi < hi)) { hv = ohv; hi = ohi; }
        }
        if (lane == 0) {
            int sel = (hv > 0.99f * bv) ? hi : bi;
            g_idx[fr] = sel + 1;
        }
    }
}

// ---------------------------------------------------------------------------
// Kernel 2: SINGLE block, 1024 threads. All 1880 medians (spill-free smem
// counting, ~2 per thread), then fixed-order two-level reduction for
// (sum f0, sum f0^2), then whiten. No cluster, no fences, no second launch.
// ---------------------------------------------------------------------------
__global__ void __launch_bounds__(1024) median_stats_kernel(float* __restrict__ out) {
    __shared__ int   rows[BATCH][PADM + KFRM];   // 8448 B
    __shared__ float f0s[BATCH * NOUT];          // 7520 B
    __shared__ float red[32][2];
    __shared__ float s_mean, s_inv;

    const int tid  = threadIdx.x;
    const int warp = tid >> 5;
    const int lane = tid & 31;
    const int N    = BATCH * NOUT;   // 1880

    // Load g_idx into padded rows
    for (int t = tid; t < BATCH * KFRM; t += 1024) {
        int b = t / KFRM, j = t - b * KFRM;
        rows[b][PADM + j] = g_idx[t];
    }
    if (tid < BATCH * PADM) {                    // replicate-pad left edge
        int b = tid / PADM, j = tid - b * PADM;
        rows[b][j] = g_idx[b * KFRM];
    }
    __syncthreads();

    // Medians: rank-14 (0-based) = smallest x with count(w <= x) >= 15
    float my0 = 0.0f, my1 = 0.0f;
    #pragma unroll
    for (int pass = 0; pass < 2; pass++) {
        int n = tid + pass * 1024;
        if (n < N) {
            int b = n / NOUT, j = n - b * NOUT;
            const int* w = rows[b] + j;
            int lo = 1, hi = LAGS + 1;
            #pragma unroll
            for (int it = 0; it < 8; it++) {
                int mid = (lo + hi) >> 1;
                int cnt = 0;
                #pragma unroll
                for (int m = 0; m < WINMED; m++) cnt += (w[m] <= mid);
                if (cnt >= PADM + 1) hi = mid; else lo = mid + 1;
            }
            float f0 = 16000.0f / (1e-9f + (float)lo);
            f0s[n] = f0;
            out[OFF_F0 + n]     = f0;
            out[OFF_VOICED + n] = 1.0f;   // idx >= 6 -> f0 > 0 always
            if (pass == 0) my0 = f0; else my1 = f0;
        }
    }

    // Fixed-order stats reduction: per-thread (2 values) -> warp -> 32 slots
    float s1 = my0 + my1;
    float s2 = my0 * my0 + my1 * my1;
    #pragma unroll
    for (int off = 16; off; off >>= 1) {
        s1 += __shfl_down_sync(0xffffffffu, s1, off);
        s2 += __shfl_down_sync(0xffffffffu, s2, off);
    }
    if (lane == 0) { red[warp][0] = s1; red[warp][1] = s2; }
    __syncthreads();
    if (tid == 0) {
        float g1 = 0.0f, g2 = 0.0f;
        #pragma unroll
        for (int wv = 0; wv < 32; wv++) { g1 += red[wv][0]; g2 += red[wv][1]; }
        float Nf   = (float)N;
        float mean = g1 / Nf;
        float ssq  = fmaxf(g2 - 2.0f * mean * g1 + Nf * mean * mean, 0.0f);
        float sd   = sqrtf(ssq / (Nf - 1.0f));
        if (sd == 0.0f) sd = 1.0f;
        s_mean = mean;
        s_inv  = 1.0f / sd;
    }
    __syncthreads();

    const float mean = s_mean, inv = s_inv;
    for (int n = tid; n < N; n += 1024)
        out[OFF_WHITEN + n] = (f0s[n] - mean) * inv;
}

extern "C" void kernel_launch(void* const* d_in, const int* in_sizes, int n_in,
                              void* d_out, int out_size) {
    const float* audio = (const float*)d_in[0];
    float* out = (float*)d_out;
    (void)in_sizes; (void)n_in; (void)out_size;

    nccf_kernel<<<BATCH * KFRM, NTHR>>>(audio, out);
    median_stats_kernel<<<1, 1024>>>(out);
}

// round 13
// speedup vs baseline: 1.3266x; 1.3266x over previous
#include <cuda_runtime.h>
#include <cstdint>

// Problem constants (fixed by setup_inputs: audio (8, 80000) fp32)
#define BATCH   8
#define TLEN    80000
#define KFRM    250
#define FRAME   320
#define LAGS    189
#define LAG_MIN 5
#define HALFSZ  94             // LAGS // 2
#define SEGLEN  509            // FRAME + LAGS
#define NOUT    235
#define WINMED  30
#define PADM    14
#define EPSF    1e-9f

// nccf kernel blocking: ONE frame per block, 96 threads (3 warps), grid 2000
#define TPF   24               // lag-groups per frame (8 lags each, 192 padded)
#define KSPL  4                // split-K factor (threads per lag-group)
#define NTHR  (TPF * KSPL)     // 96 threads
#define NLAGP 192
#define SEGL  520              // logical padded segment length
#define SEGP  584              // physical (skewed) words per frame

// output layout (float32): f0[B*NOUT], whiten[B*NOUT], voiced[B*NOUT], energy[B*KFRM]
#define OFF_F0     0
#define OFF_WHITEN (BATCH * NOUT)
#define OFF_VOICED (2 * BATCH * NOUT)
#define OFF_ENERGY (3 * BATCH * NOUT)

__device__ int g_idx[BATCH * KFRM];

typedef unsigned long long ull;

__device__ __forceinline__ int skew(int m) { return m + ((m >> 5) << 2); }

__device__ __forceinline__ ull pk(float lo, float hi) {
    ull r; asm("mov.b64 %0, {%1, %2};" : "=l"(r) : "f"(lo), "f"(hi)); return r;
}
__device__ __forceinline__ void upk(float& lo, float& hi, ull v) {
    asm("mov.b64 {%0, %1}, %2;" : "=f"(lo), "=f"(hi) : "l"(v));
}
__device__ __forceinline__ void ffma2(ull& d, ull a, ull b) {
    asm("fma.rn.f32x2 %0, %1, %2, %0;" : "+l"(d) : "l"(a), "l"(b));
}

// ---------------------------------------------------------------------------
// Kernel 1 (R11, 11.8us + PDL trigger): NCCF + argmax + energy.
// ONE frame per block, 96 threads, grid 2000. Prefix-sum-of-x^2 for norms;
// mainloop 16 FFMA2/step fully unrolled; 4 K-partials combined via shfl_xor.
// After the g_idx store each block signals griddepcontrol.launch_dependents
// so the PDL-launched tail kernel can proceed.
// ---------------------------------------------------------------------------
__global__ void __launch_bounds__(NTHR) nccf_kernel(const float* __restrict__ audio,
                                                    float* __restrict__ out) {
    __shared__ __align__(16) float seg[SEGP];
    __shared__ float P[516];          // P[j] = sum_{i<j} x_i^2, j in [0, 510]
    __shared__ float wsum[3];
    __shared__ float sval[NLAGP];

    const int tid  = threadIdx.x;
    const int warp = tid >> 5;
    const int lane = tid & 31;
    const int fr   = blockIdx.x;           // frame id = b*KFRM + k

    // Stage this frame (skewed layout, zero-padded)
    {
        const int b = fr / KFRM;
        const int k = fr - b * KFRM;
        const float* row  = audio + (size_t)b * TLEN;
        const int    base = k * FRAME;
        for (int j = tid; j < SEGL; j += NTHR) {
            float v = 0.0f;
            if (j < SEGLEN && base + j < TLEN) v = row[base + j];
            seg[skew(j)] = v;
        }
    }
    __syncthreads();

    // Prefix sum of x^2 over j in [0, 510): thread owns 6 elements
    {
        const int j0 = tid * 6;
        float pre[6];
        float sum = 0.0f;
        #pragma unroll
        for (int k = 0; k < 6; k++) {
            float x = 0.0f;
            if (j0 + k < 510) x = seg[skew(j0 + k)];
            sum = fmaf(x, x, sum);
            pre[k] = sum;
        }
        float sc = sum;   // inclusive warp scan of per-thread totals
        #pragma unroll
        for (int d = 1; d < 32; d <<= 1) {
            float o = __shfl_up_sync(0xffffffffu, sc, d);
            if (lane >= d) sc += o;
        }
        if (lane == 31) wsum[warp] = sc;
        __syncthreads();
        float base = sc - sum;
        if (warp >= 1) base += wsum[0];
        if (warp >= 2) base += wsum[1];
        if (tid == 0) P[0] = 0.0f;
        #pragma unroll
        for (int k = 0; k < 6; k++)
            if (j0 + k < 510) P[j0 + k + 1] = base + pre[k];
    }
    __syncthreads();

    {
        const int h  = tid & 3;                 // K-chunk
        const int g  = tid >> 2;                // lag-group 0..23
        const float* sf = seg;
        const int gb = 8 * g;
        const int sb = 20 * h;                  // window-step base

        ull c0 = 0, c1 = 0, c2 = 0, c3 = 0, c4 = 0, c5 = 0, c6 = 0, c7 = 0;
        float4 W1;
        ull O0, O1, O2, E1, E2, E3;
        {
            float4 W0 = *reinterpret_cast<const float4*>(sf + skew(gb + 4 * sb));
            W1        = *reinterpret_cast<const float4*>(sf + skew(gb + 4 * sb + 4));
            O0 = pk(W0.y, W0.z); O1 = pk(W0.w, W1.x); O2 = pk(W1.y, W1.z);
            E1 = pk(W0.z, W0.w); E2 = pk(W1.x, W1.y); E3 = pk(W1.z, W1.w);
        }

        #pragma unroll
        for (int s = 0; s < 20; s++) {
            float4 Aq = *reinterpret_cast<const float4*>(sf + skew(4 * (sb + s)));
            ull A01 = pk(Aq.x, Aq.y);
            ull A23 = pk(Aq.z, Aq.w);
            float4 W2 = *reinterpret_cast<const float4*>(sf + skew(gb + 8 + 4 * (sb + s)));

            ull O3 = pk(W1.w, W2.x);
            ull E4 = pk(W2.x, W2.y);
            ull O4 = pk(W2.y, W2.z);
            ull E5 = pk(W2.z, W2.w);

            ffma2(c0, A01, O0); ffma2(c0, A23, O1);
            ffma2(c1, A01, E1); ffma2(c1, A23, E2);
            ffma2(c2, A01, O1); ffma2(c2, A23, O2);
            ffma2(c3, A01, E2); ffma2(c3, A23, E3);
            ffma2(c4, A01, O2); ffma2(c4, A23, O3);
            ffma2(c5, A01, E3); ffma2(c5, A23, E4);
            ffma2(c6, A01, O3); ffma2(c6, A23, O4);
            ffma2(c7, A01, E4); ffma2(c7, A23, E5);

            O0 = O2; O1 = O3; O2 = O4;
            E1 = E3; E2 = E4; E3 = E5;
            W1 = W2;
        }

        // Reduce packed pairs to scalars, then combine K-partials via shfl.
        float cr[8];
        { float lo, hi;
          upk(lo, hi, c0); cr[0] = lo + hi; upk(lo, hi, c1); cr[1] = lo + hi;
          upk(lo, hi, c2); cr[2] = lo + hi; upk(lo, hi, c3); cr[3] = lo + hi;
          upk(lo, hi, c4); cr[4] = lo + hi; upk(lo, hi, c5); cr[5] = lo + hi;
          upk(lo, hi, c6); cr[6] = lo + hi; upk(lo, hi, c7); cr[7] = lo + hi; }
        #pragma unroll
        for (int d = 1; d <= 2; d <<= 1) {
            #pragma unroll
            for (int l = 0; l < 8; l++)
                cr[l] += __shfl_xor_sync(0xffffffffu, cr[l], d);
        }

        // norms from prefix sums; each h-thread writes 2 of the 8 lags
        #pragma unroll
        for (int l = 2 * h; l < 2 * h + 2; l++) {
            int t = gb + l;
            float n2 = fmaxf(P[t + 321] - P[t + 1], 0.0f);
            float d  = EPSF + sqrtf(n2);
            sval[t] = __fdividef(cr[l], d * d);
        }

        if (tid == 0)
            out[OFF_ENERGY + fr] = P[320] * (1.0f / FRAME);
    }
    __syncthreads();

    // Argmax (warp 0, first-occurrence semantics)
    if (warp == 0) {
        float bv = -3.0e38f; int bi = 1 << 30;
        float hv = -3.0e38f; int hi = 1 << 30;
        for (int t = LAG_MIN + lane; t < LAGS; t += 32) {
            float x = sval[t];
            if (x > bv) { bv = x; bi = t; }
            if (t < HALFSZ && x > hv) { hv = x; hi = t; }
        }
        #pragma unroll
        for (int off = 16; off; off >>= 1) {
            float ov  = __shfl_down_sync(0xffffffffu, bv, off);
            int   oi  = __shfl_down_sync(0xffffffffu, bi, off);
            if (ov > bv || (ov == bv && oi < bi)) { bv = ov; bi = oi; }
            float ohv = __shfl_down_sync(0xffffffffu, hv, off);
            int   ohi = __shfl_down_sync(0xffffffffu, hi, off);
            if (ohv > hv || (ohv == hv && ohi < hi)) { hv = ohv; hi = ohi; }
        }
        if (lane == 0) {
            int sel = (hv > 0.99f * bv) ? hi : bi;
            g_idx[fr] = sel + 1;
        }
    }

    // PDL: this block's g_idx contribution is done -> let dependents schedule.
    asm volatile("griddepcontrol.launch_dependents;");
}

// ---------------------------------------------------------------------------
// Kernel 2 (8-CTA cluster, PDL consumer): waits on griddepcontrol (all nccf
// blocks done -> g_idx visible), then CTA b computes batch row b's medians
// -> f0/voiced, exchanges (sum, sum^2) via mapa/st.cluster slots, cluster-
// syncs, combines in fixed order, writes whiten.
// ---------------------------------------------------------------------------
__global__ void __launch_bounds__(256) __cluster_dims__(BATCH, 1, 1)
median_stats_kernel(float* __restrict__ out) {
    const int b = blockIdx.x;
    const int tid = threadIdx.x;
    __shared__ int    row[PADM + KFRM];
    __shared__ float  f0row[NOUT];
    __shared__ float  wred[8][2];
    __shared__ __align__(8) float slots[BATCH][2];   // same offset in every CTA

    // Gate on the producer grid (PDL). Writes before launch_dependents in
    // nccf are visible after this wait.
    asm volatile("griddepcontrol.wait;" ::: "memory");

    for (int t = tid; t < PADM + KFRM; t += 256) {
        int p = t - PADM;
        row[t] = g_idx[b * KFRM + (p < 0 ? 0 : p)];
    }
    __syncthreads();

    float f0 = 0.0f;
    if (tid < NOUT) {
        const int* w = row + tid;
        // rank-14 (0-based) = smallest x with count(w <= x) >= 15
        int lo = 1, hi = LAGS + 1;
        #pragma unroll
        for (int it = 0; it < 8; it++) {
            int mid = (lo + hi) >> 1;
            int cnt = 0;
            #pragma unroll
            for (int m = 0; m < WINMED; m++) cnt += (w[m] <= mid);
            if (cnt >= PADM + 1) hi = mid; else lo = mid + 1;
        }
        f0 = 16000.0f / (1e-9f + (float)lo);
        f0row[tid] = f0;
        out[OFF_F0 + b * NOUT + tid]     = f0;
        out[OFF_VOICED + b * NOUT + tid] = 1.0f;   // idx >= 6 -> f0 > 0 always
    }

    // Row partial sums s1 = sum f0, s2 = sum f0^2 (fixed reduction order)
    float s1 = f0, s2 = f0 * f0;
    #pragma unroll
    for (int off = 16; off; off >>= 1) {
        s1 += __shfl_down_sync(0xffffffffu, s1, off);
        s2 += __shfl_down_sync(0xffffffffu, s2, off);
    }
    if ((tid & 31) == 0) { wred[tid >> 5][0] = s1; wred[tid >> 5][1] = s2; }
    __syncthreads();

    if (tid == 0) {
        float t1 = 0.0f, t2 = 0.0f;
        #pragma unroll
        for (int wv = 0; wv < 8; wv++) { t1 += wred[wv][0]; t2 += wred[wv][1]; }
        ull pair; asm("mov.b64 %0, {%1, %2};" : "=l"(pair) : "f"(t1), "f"(t2));
        unsigned int laddr;
        asm("{ .reg .u64 a; cvta.to.shared.u64 a, %1; cvt.u32.u64 %0, a; }"
            : "=r"(laddr) : "l"(&slots[b][0]));
        #pragma unroll
        for (int p = 0; p < BATCH; p++) {
            unsigned int raddr;
            asm("mapa.shared::cluster.u32 %0, %1, %2;" : "=r"(raddr) : "r"(laddr), "r"(p));
            asm volatile("st.shared::cluster.b64 [%0], %1;" :: "r"(raddr), "l"(pair) : "memory");
        }
    }
    __syncthreads();
    asm volatile("barrier.cluster.arrive.aligned;" ::: "memory");
    asm volatile("barrier.cluster.wait.aligned;"   ::: "memory");

    // Combine the 8 slots in fixed order -> identical mean/std in every CTA
    const float N = (float)(BATCH * NOUT);   // 1880
    float g1 = 0.0f, g2 = 0.0f;
    #pragma unroll
    for (int p = 0; p < BATCH; p++) { g1 += slots[p][0]; g2 += slots[p][1]; }
    float mean = g1 / N;
    float ssq = fmaxf(g2 - 2.0f * mean * g1 + N * mean * mean, 0.0f);
    float sd  = sqrtf(ssq / (N - 1.0f));
    if (sd == 0.0f) sd = 1.0f;
    float inv = 1.0f / sd;

    if (tid < NOUT)
        out[OFF_WHITEN + b * NOUT + tid] = (f0row[tid] - mean) * inv;
}

extern "C" void kernel_launch(void* const* d_in, const int* in_sizes, int n_in,
                              void* d_out, int out_size) {
    const float* audio = (const float*)d_in[0];
    float* out = (float*)d_out;
    (void)in_sizes; (void)n_in; (void)out_size;

    nccf_kernel<<<BATCH * KFRM, NTHR>>>(audio, out);

    // Tail: PDL launch so its setup overlaps nccf execution.
    cudaLaunchConfig_t cfg = {};
    cfg.gridDim  = dim3(BATCH, 1, 1);
    cfg.blockDim = dim3(256, 1, 1);
    cfg.dynamicSmemBytes = 0;
    cudaLaunchAttribute attrs[1];
    attrs[0].id = cudaLaunchAttributeProgrammaticStreamSerialization;
    attrs[0].val.programmaticStreamSerializationAllowed = 1;
    cfg.attrs = attrs;
    cfg.numAttrs = 1;
    cudaLaunchKernelEx(&cfg, median_stats_kernel, out);
}